// round 15
// baseline (speedup 1.0000x reference)
#include <cuda_runtime.h>

namespace {

constexpr int BATCH   = 4;
constexpr int NIN     = 1024;
constexpr int NOUT    = 1024;
constexpr int CH      = 8;     // density + 7 raw channels
constexpr int OC      = 16;
constexpr int OPB     = 256;   // outputs per block (32 per warp)
constexpr int OG      = NOUT / OPB;        // 4 output groups
constexpr int SPLITS  = 32;    // i-dimension splits across blocks
constexpr int ISPB    = NIN / SPLITS;      // 32 i per block
constexpr int THREADS = 256;
constexpr int WARPS   = THREADS / 32;      // 8
constexpr int SLOT    = OPB * CH;          // 2048 floats per (group, split)

// Partial aggregates: [(b*OG+og)*SPLITS + split][o_local*8 + c]  (4 MB)
__device__ float g_part[BATCH * OG * SPLITS * SLOT];
// Per-(b,og) completion counters (zero-init; finisher resets -> replay-safe)
__device__ int   g_count[BATCH * OG];

__device__ __forceinline__ float ex2_approx(float x) {
    float y;
    asm("ex2.approx.f32 %0, %1;" : "=f"(y) : "f"(x));
    return y;
}

// --------- Fused kernel: warp-per-32-outputs, last-block finish ---------
__global__ __launch_bounds__(THREADS, 5)
void convdeepset_kernel(const float* __restrict__ cx,     // [B, NIN, 1]
                        const float* __restrict__ cy,     // [B, NIN, 7]
                        const float* __restrict__ t,      // [B, NOUT, 1]
                        const float* __restrict__ sigma,  // [8]
                        const float* __restrict__ W,      // [8, 16]
                        const float* __restrict__ bias,   // [16]
                        float* __restrict__ out)          // [B*NOUT, 16]
{
    // sy[i] = [y1..y7, 1.0] -> two broadcast LDS.128 per i
    __shared__ float  sy[ISPB][CH];              // 1 KB
    __shared__ float  sx[ISPB];                  // 128 B (pre-scaled x)
    __shared__ float  sbeta[CH];
    __shared__ float  sagg [OPB][CH];            // 8 KB (finisher)
    __shared__ float  sagg2[OPB][CH];            // 8 KB (finisher)
    __shared__ int    s_last;

    const int bi    = blockIdx.x;
    const int b     = bi >> 7;                   // / (OG*SPLITS)
    const int og    = (bi >> 5) & 3;
    const int split = bi & 31;
    const int tid   = threadIdx.x;
    const int warp  = tid >> 5;
    const int lane  = tid & 31;
    const int i0    = split * ISPB;

    // ---- parallel prologue (R14 lesson: never serialize on tid0) ----
    if (tid < CH) {
        float s = expf(sigma[tid]);
        sbeta[tid] = -0.5f * 1.4426950408889634f / (s * s);
    }
    // Every thread computes kscale independently (parallel, ~30 issues)
    const float kscale = sqrtf(0.5f * 1.4426950408889634f) / expf(sigma[0]);

    // ---- staging: exactly one y slot per thread, x by warp 0 ----
    {
        int i = tid >> 3, c = tid & 7;           // 32 i x 8 c = 256 slots
        sy[i][c] = (c < 7) ? cy[(b * NIN + i0 + i) * 7 + c] : 1.0f;
    }
    if (tid < ISPB) sx[tid] = kscale * cx[b * NIN + i0 + tid];

    const int G  = b * OG + og;                  // group index
    const int G0 = b * NOUT + og * OPB;          // first global output
    const int o_l = warp * 32 + lane;            // owned output in group
    const float t_k = kscale * t[G0 + o_l];
    __syncthreads();

    const float beta0 = sbeta[0];
    bool uni = true;
    #pragma unroll
    for (int c = 1; c < CH; c++) uni &= (sbeta[c] == beta0);

    // Accumulators in y-slot order: [y1..y7, den]
    float acc[CH];
    #pragma unroll
    for (int c = 0; c < CH; c++) acc[c] = 0.0f;

    const float4* xw4 = reinterpret_cast<const float4*>(&sx[0]);
    const float4* yw  = reinterpret_cast<const float4*>(&sy[0][0]);

    if (uni) {
        #pragma unroll
        for (int jc = 0; jc < ISPB / 4; jc++) {
            // 4 independent exp chains (MUFU pipelines at rt=8)
            float4 x4 = xw4[jc];                 // one broadcast LDS.128
            float d0 = x4.x - t_k;
            float d1 = x4.y - t_k;
            float d2 = x4.z - t_k;
            float d3 = x4.w - t_k;
            float w0 = ex2_approx(d0 * -d0);
            float w1 = ex2_approx(d1 * -d1);
            float w2 = ex2_approx(d2 * -d2);
            float w3 = ex2_approx(d3 * -d3);
            #pragma unroll
            for (int u = 0; u < 4; u++) {
                int j = jc * 4 + u;
                float w = (u == 0) ? w0 : (u == 1) ? w1 : (u == 2) ? w2 : w3;
                float4 p0 = yw[2 * j];           // {y1,y2,y3,y4} broadcast
                float4 p1 = yw[2 * j + 1];       // {y5,y6,y7,1}
                acc[0] += p0.x * w;  acc[1] += p0.y * w;
                acc[2] += p0.z * w;  acc[3] += p0.w * w;
                acc[4] += p1.x * w;  acc[5] += p1.y * w;
                acc[6] += p1.z * w;  acc[7] += w;        // density: y==1
            }
        }
    } else {
        // General path: exponent_c = (beta_c/beta0)*a, a = beta0*d_raw^2
        float ratio[CH];
        #pragma unroll
        for (int c = 0; c < CH; c++) ratio[c] = sbeta[c] / beta0;
        const float* yws = &sy[0][0];
        const float* xw  = &sx[0];
        #pragma unroll 2
        for (int j = 0; j < ISPB; j++) {
            float d = xw[j] - t_k;
            float a = d * -d;                    // = beta0 * d_raw^2
            #pragma unroll
            for (int c = 0; c < 7; c++)
                acc[c] += yws[j * CH + c] * ex2_approx(ratio[c + 1] * a);
            acc[7] += ex2_approx(ratio[0] * a);  // density
        }
    }

    // ---- direct partial write: canonical order [den, y1..y7] ----
    {
        float4* dst = reinterpret_cast<float4*>(
            &g_part[(G * SPLITS + split) * SLOT + o_l * CH]);
        dst[0] = make_float4(acc[7], acc[0], acc[1], acc[2]);
        dst[1] = make_float4(acc[3], acc[4], acc[5], acc[6]);
    }

    // ---- last-block-done gate (threadFenceReduction pattern) ----
    __threadfence();
    __syncthreads();                             // all warps' STGs issued
    if (tid == 0) {
        int old = atomicAdd(&g_count[G], 1);
        s_last = (old == SPLITS - 1);
        if (s_last) g_count[G] = 0;              // reset for next replay
    }
    __syncthreads();
    if (!s_last) return;

    // ---- finish phase 1: sum 32 splits (float4, high MLP) ----
    {
        const float* pb = &g_part[G * SPLITS * SLOT];
        #pragma unroll
        for (int rr = 0; rr < 2; rr++) {
            int s = tid + rr * THREADS;          // 512 quad-slots
            int o = s >> 1, q = s & 1;
            const float4* p = reinterpret_cast<const float4*>(
                pb + o * CH + q * 4);
            float4 acc4 = make_float4(0.f, 0.f, 0.f, 0.f);
            #pragma unroll 8
            for (int sp = 0; sp < SPLITS; sp++) {
                float4 v = p[sp * (SLOT / 4)];
                acc4.x += v.x; acc4.y += v.y; acc4.z += v.z; acc4.w += v.w;
            }
            *reinterpret_cast<float4*>(&sagg[o][q * 4]) = acc4;
        }
    }
    __syncthreads();

    // ---- finish phase 2: normalize ----
    #pragma unroll
    for (int rr = 0; rr < 8; rr++) {
        int idx = tid + rr * THREADS;            // 2048 slots
        int o = idx >> 3, c = idx & 7;
        float den = sagg[o][0];
        float v = sagg[o][c];
        sagg2[o][c] = (c == 0) ? den : v / (den + 1e-8f);
    }
    __syncthreads();

    // ---- finish phase 3: out[G0+o][k] = bias[k] + sum_c agg2*W ----
    #pragma unroll
    for (int rr = 0; rr < 16; rr++) {
        int idx = tid + rr * THREADS;            // 4096 slots
        int o = idx >> 4, k = idx & 15;
        float v = __ldg(&bias[k]);
        #pragma unroll
        for (int c = 0; c < CH; c++) v += sagg2[o][c] * __ldg(&W[c * OC + k]);
        out[(G0 + o) * OC + k] = v;              // coalesced
    }
}

} // namespace

extern "C" void kernel_launch(void* const* d_in, const int* in_sizes, int n_in,
                              void* d_out, int out_size) {
    const float* cx = (const float*)d_in[0];  // context_x
    const float* cy = (const float*)d_in[1];  // context_y
    const float* t  = (const float*)d_in[2];  // t
    const float* sg = (const float*)d_in[3];  // sigma
    const float* W  = (const float*)d_in[4];  // W
    const float* bi = (const float*)d_in[5];  // b
    float* out = (float*)d_out;

    convdeepset_kernel<<<BATCH * OG * SPLITS, THREADS>>>(cx, cy, t, sg, W, bi, out);
}

// round 16
// speedup vs baseline: 1.6149x; 1.6149x over previous
#include <cuda_runtime.h>
#include <cuda_fp16.h>

namespace {

constexpr int BATCH   = 4;
constexpr int NIN     = 1024;
constexpr int NOUT    = 1024;
constexpr int CH      = 8;     // density + 7 raw channels
constexpr int OC      = 16;
constexpr int OPB     = 128;   // outputs per block (16 per warp)
constexpr int OG      = NOUT / OPB;        // 8 output groups
constexpr int SPLITS  = 16;    // i-dimension splits across blocks
constexpr int ISPB    = NIN / SPLITS;      // 64 i per block
constexpr int THREADS = 256;
constexpr int WARPS   = THREADS / 32;      // 8
constexpr int KSTEPS  = ISPB / 16;         // 4 mma k-steps
constexpr int SLOT    = OPB * CH;          // 1024 floats per (group, split)

// Partial aggregates: [(b*OG+og)*SPLITS+split][o_local*CH+c]  (2 MB)
__device__ float g_part[BATCH * OG * SPLITS * SLOT];
// Per-(b,og) completion counters (zero-init; finisher resets -> replay-safe)
__device__ int   g_count[BATCH * OG];

__device__ __forceinline__ float ex2_approx(float x) {
    float y;
    asm("ex2.approx.f32 %0, %1;" : "=f"(y) : "f"(x));
    return y;
}

// pack two f32 into f16x2: lo = a, hi = b
__device__ __forceinline__ unsigned int pack_h2(float lo, float hi) {
    unsigned int r;
    asm("cvt.rn.f16x2.f32 %0, %1, %2;" : "=r"(r) : "f"(hi), "f"(lo));
    return r;
}

__device__ __forceinline__ void mma_16816(float& d0, float& d1, float& d2, float& d3,
                                          unsigned int a0, unsigned int a1,
                                          unsigned int a2, unsigned int a3,
                                          unsigned int b0, unsigned int b1) {
    asm volatile(
        "mma.sync.aligned.m16n8k16.row.col.f32.f16.f16.f32 "
        "{%0,%1,%2,%3}, {%4,%5,%6,%7}, {%8,%9}, {%0,%1,%2,%3};"
        : "+f"(d0), "+f"(d1), "+f"(d2), "+f"(d3)
        : "r"(a0), "r"(a1), "r"(a2), "r"(a3), "r"(b0), "r"(b1));
}

// --------- Fused kernel: tensor-core aggregation + last-block finish ---------
__global__ __launch_bounds__(THREADS, 5)
void convdeepset_kernel(const float* __restrict__ cx,     // [B, NIN, 1]
                        const float* __restrict__ cy,     // [B, NIN, 7]
                        const float* __restrict__ t,      // [B, NOUT, 1]
                        const float* __restrict__ sigma,  // [8]
                        const float* __restrict__ W,      // [8, 16]
                        const float* __restrict__ bias,   // [16]
                        float* __restrict__ out)          // [B*NOUT, 16]
{
    __shared__ float        sx[ISPB];                // 256 B (pre-scaled x)
    __shared__ unsigned int sYh[ISPB / 2][CH];       // 1 KB f16x2 {y[2kp],y[2kp+1]} per ch
    __shared__ float        sagg [OPB][CH];          // 4 KB (finisher)
    __shared__ float        sagg2[OPB][CH];          // 4 KB (finisher)
    __shared__ int          s_last;

    const int bi    = blockIdx.x;
    const int b     = bi >> 7;                       // / (OG*SPLITS)
    const int og    = (bi >> 4) & 7;
    const int split = bi & 15;
    const int tid   = threadIdx.x;
    const int warp  = tid >> 5;
    const int lane  = tid & 31;
    const int g     = lane >> 2;                     // mma group id (0..7)
    const int tq    = lane & 3;                      // thread in group
    const int i0    = split * ISPB;

    // Parallel prologue (R14 lesson: never serialize on tid0)
    const float L2E = 1.4426950408889634f;
    const float sg0 = sigma[0];
    const float kscale = sqrtf(0.5f * L2E) / expf(sg0);
    bool uni = true;
    #pragma unroll
    for (int c = 1; c < CH; c++) uni &= (sigma[c] == sg0);

    // Stage x (pre-scaled) and Yext packed to f16x2 pairs along i
    if (tid < ISPB) sx[tid] = kscale * cx[b * NIN + i0 + tid];
    {
        int kp = tid >> 3, c = tid & 7;              // 32 pairs x 8 ch = 256 slots
        int ig = b * NIN + i0 + kp * 2;
        float ya = (c == 0) ? 1.0f : cy[ig * 7 + (c - 1)];
        float yb = (c == 0) ? 1.0f : cy[(ig + 1) * 7 + (c - 1)];
        sYh[kp][c] = pack_h2(ya, yb);                // lo = even i, hi = odd i
    }

    const int G  = b * OG + og;
    const int G0 = b * NOUT + og * OPB;
    float* gp = &g_part[(G * SPLITS + split) * SLOT];
    __syncthreads();

    if (uni) {
        // t values for this lane's two A rows (outputs g and g+8 of warp tile)
        const float tk0 = kscale * t[G0 + warp * 16 + g];
        const float tk1 = kscale * t[G0 + warp * 16 + g + 8];

        float d0 = 0.f, d1 = 0.f, d2 = 0.f, d3 = 0.f;

        #pragma unroll
        for (int s = 0; s < KSTEPS; s++) {
            const int k0 = s * 16;
            // x for this lane's 4 A-columns: k = 2t, 2t+1, 2t+8, 2t+9
            float2 xa = *reinterpret_cast<const float2*>(&sx[k0 + tq * 2]);
            float2 xb = *reinterpret_cast<const float2*>(&sx[k0 + tq * 2 + 8]);
            // 8 independent exp chains (irreducible MUFU work)
            float e0 = xa.x - tk0, e1 = xa.y - tk0;
            float e2 = xb.x - tk0, e3 = xb.y - tk0;
            float f0 = xa.x - tk1, f1 = xa.y - tk1;
            float f2 = xb.x - tk1, f3 = xb.y - tk1;
            float w00 = ex2_approx(e0 * -e0);
            float w01 = ex2_approx(e1 * -e1);
            float w02 = ex2_approx(e2 * -e2);
            float w03 = ex2_approx(e3 * -e3);
            float w10 = ex2_approx(f0 * -f0);
            float w11 = ex2_approx(f1 * -f1);
            float w12 = ex2_approx(f2 * -f2);
            float w13 = ex2_approx(f3 * -f3);
            // A fragment: a0 = row g  cols 2t,2t+1; a1 = row g+8 cols 2t,2t+1
            //             a2 = row g  cols +8,+9;  a3 = row g+8 cols +8,+9
            unsigned int a0 = pack_h2(w00, w01);
            unsigned int a1 = pack_h2(w10, w11);
            unsigned int a2 = pack_h2(w02, w03);
            unsigned int a3 = pack_h2(w12, w13);
            // B fragment: col g, rows 2t,2t+1 and 2t+8,2t+9 (pre-packed pairs)
            unsigned int b0 = sYh[(k0 >> 1) + tq][g];
            unsigned int b1 = sYh[(k0 >> 1) + 4 + tq][g];
            mma_16816(d0, d1, d2, d3, a0, a1, a2, a3, b0, b1);
        }

        // D fragment: d0,d1 -> row g, ch 2t,2t+1; d2,d3 -> row g+8 same ch
        *reinterpret_cast<float2*>(&gp[(warp * 16 + g) * CH + tq * 2]) =
            make_float2(d0, d1);
        *reinterpret_cast<float2*>(&gp[(warp * 16 + g + 8) * CH + tq * 2]) =
            make_float2(d2, d3);
    } else {
        // Correctness-only fallback (general sigma): scalar fp32 path.
        float betas[CH];
        #pragma unroll
        for (int c = 0; c < CH; c++) {
            float sv = expf(sigma[c]);
            betas[c] = -0.5f * L2E / (sv * sv);
        }
        float ratio[CH];
        #pragma unroll
        for (int c = 0; c < CH; c++) ratio[c] = betas[c] / betas[0];

        const int o_idx = lane & 15;                 // output within warp tile
        const int ihalf = lane >> 4;                 // i half (0/1)
        const float tk = kscale * t[G0 + warp * 16 + o_idx];
        float acc[CH];                               // canonical [den, y1..y7]
        #pragma unroll
        for (int c = 0; c < CH; c++) acc[c] = 0.0f;
        for (int j = ihalf * (ISPB / 2); j < (ihalf + 1) * (ISPB / 2); j++) {
            float d = sx[j] - tk;
            float a = d * -d;                        // = beta0 * d_raw^2
            acc[0] += ex2_approx(ratio[0] * a);
            const float* yrow = &cy[(b * NIN + i0 + j) * 7];
            #pragma unroll
            for (int c = 1; c < CH; c++)
                acc[c] += yrow[c - 1] * ex2_approx(ratio[c] * a);
        }
        #pragma unroll
        for (int c = 0; c < CH; c++)
            acc[c] += __shfl_xor_sync(0xffffffffu, acc[c], 16);
        if (lane < 16) {
            float4* dst = reinterpret_cast<float4*>(
                &gp[(warp * 16 + o_idx) * CH]);
            dst[0] = make_float4(acc[0], acc[1], acc[2], acc[3]);
            dst[1] = make_float4(acc[4], acc[5], acc[6], acc[7]);
        }
    }

    // ---- last-block-done gate (threadFenceReduction pattern) ----
    __threadfence();
    __syncthreads();
    if (tid == 0) {
        int old = atomicAdd(&g_count[G], 1);
        s_last = (old == SPLITS - 1);
        if (s_last) g_count[G] = 0;                  // reset for next replay
    }
    __syncthreads();
    if (!s_last) return;

    // ---- finish phase 1: sum 16 splits (float4, high MLP) ----
    {
        const float* pb = &g_part[G * SPLITS * SLOT];
        int o = tid >> 1, q = tid & 1;               // 128 o x 2 quads
        const float4* p = reinterpret_cast<const float4*>(pb + o * CH + q * 4);
        float4 a4 = make_float4(0.f, 0.f, 0.f, 0.f);
        #pragma unroll
        for (int sp = 0; sp < SPLITS; sp++) {
            float4 v = p[sp * (SLOT / 4)];
            a4.x += v.x; a4.y += v.y; a4.z += v.z; a4.w += v.w;
        }
        *reinterpret_cast<float4*>(&sagg[o][q * 4]) = a4;
    }
    __syncthreads();

    // ---- finish phase 2: normalize ----
    #pragma unroll
    for (int rr = 0; rr < 4; rr++) {
        int idx = tid + rr * THREADS;                // 1024 slots
        int o = idx >> 3, c = idx & 7;
        float den = sagg[o][0];
        float v = sagg[o][c];
        sagg2[o][c] = (c == 0) ? den : v / (den + 1e-8f);
    }
    __syncthreads();

    // ---- finish phase 3: out[G0+o][k] = bias[k] + sum_c agg2*W ----
    #pragma unroll
    for (int rr = 0; rr < 8; rr++) {
        int idx = tid + rr * THREADS;                // 2048 slots
        int o = idx >> 4, k = idx & 15;
        float v = __ldg(&bias[k]);
        #pragma unroll
        for (int c = 0; c < CH; c++) v += sagg2[o][c] * __ldg(&W[c * OC + k]);
        out[(G0 + o) * OC + k] = v;                  // coalesced
    }
}

} // namespace

extern "C" void kernel_launch(void* const* d_in, const int* in_sizes, int n_in,
                              void* d_out, int out_size) {
    const float* cx = (const float*)d_in[0];  // context_x
    const float* cy = (const float*)d_in[1];  // context_y
    const float* t  = (const float*)d_in[2];  // t
    const float* sg = (const float*)d_in[3];  // sigma
    const float* W  = (const float*)d_in[4];  // W
    const float* bi = (const float*)d_in[5];  // b
    float* out = (float*)d_out;

    convdeepset_kernel<<<BATCH * OG * SPLITS, THREADS>>>(cx, cy, t, sg, W, bi, out);
}

// round 17
// speedup vs baseline: 1.6199x; 1.0031x over previous
#include <cuda_runtime.h>
#include <cuda_fp16.h>

namespace {

constexpr int BATCH   = 4;
constexpr int NIN     = 1024;
constexpr int NOUT    = 1024;
constexpr int CH      = 8;     // density + 7 raw channels
constexpr int OC      = 16;
constexpr int OPB     = 16;    // outputs per block (one m16 tile, all warps)
constexpr int OG      = NOUT / OPB;        // 64 output groups per batch
constexpr int SPLITS  = 2;     // i halves
constexpr int ISPB    = NIN / SPLITS;      // 512 i per block
constexpr int THREADS = 256;
constexpr int WARPS   = THREADS / 32;      // 8
constexpr int IPW     = ISPB / WARPS;      // 64 i per warp
constexpr int KSTEPS  = IPW / 16;          // 4 mma k-steps per warp
constexpr int SLOT    = OPB * CH;          // 128 floats per (group, split)

// Partial aggregates: [(b*OG+og)*SPLITS+split][o_local*CH+c]  (256 KB)
__device__ float g_part[BATCH * OG * SPLITS * SLOT];
// Per-(b,og) completion counters (zero-init; finisher resets -> replay-safe)
__device__ int   g_count[BATCH * OG];

__device__ __forceinline__ float ex2_approx(float x) {
    float y;
    asm("ex2.approx.f32 %0, %1;" : "=f"(y) : "f"(x));
    return y;
}

// pack two f32 into f16x2: lo = a, hi = b
__device__ __forceinline__ unsigned int pack_h2(float lo, float hi) {
    unsigned int r;
    asm("cvt.rn.f16x2.f32 %0, %1, %2;" : "=r"(r) : "f"(hi), "f"(lo));
    return r;
}

__device__ __forceinline__ void mma_16816(float& d0, float& d1, float& d2, float& d3,
                                          unsigned int a0, unsigned int a1,
                                          unsigned int a2, unsigned int a3,
                                          unsigned int b0, unsigned int b1) {
    asm volatile(
        "mma.sync.aligned.m16n8k16.row.col.f32.f16.f16.f32 "
        "{%0,%1,%2,%3}, {%4,%5,%6,%7}, {%8,%9}, {%0,%1,%2,%3};"
        : "+f"(d0), "+f"(d1), "+f"(d2), "+f"(d3)
        : "r"(a0), "r"(a1), "r"(a2), "r"(a3), "r"(b0), "r"(b1));
}

// --------- Fused kernel: tensor-core aggregation + 2-way split gate ---------
__global__ __launch_bounds__(THREADS, 5)
void convdeepset_kernel(const float* __restrict__ cx,     // [B, NIN, 1]
                        const float* __restrict__ cy,     // [B, NIN, 7]
                        const float* __restrict__ t,      // [B, NOUT, 1]
                        const float* __restrict__ sigma,  // [8]
                        const float* __restrict__ W,      // [8, 16]
                        const float* __restrict__ bias,   // [16]
                        float* __restrict__ out)          // [B*NOUT, 16]
{
    __shared__ float        sx[ISPB];                // 2 KB (pre-scaled x)
    __shared__ unsigned int sYh[ISPB / 2][CH];       // 8 KB f16x2 pairs per ch
    __shared__ float        spart[WARPS][OPB][CH];   // 4 KB cross-warp partials
    __shared__ float        sagg2[OPB][CH];          // 512 B (finisher)
    __shared__ int          s_last;

    const int bi    = blockIdx.x;
    const int b     = bi >> 7;                       // / (OG*SPLITS)
    const int og    = (bi >> 1) & 63;
    const int split = bi & 1;
    const int tid   = threadIdx.x;
    const int warp  = tid >> 5;
    const int lane  = tid & 31;
    const int g     = lane >> 2;                     // mma group id (0..7)
    const int tq    = lane & 3;                      // thread in group
    const int i0    = split * ISPB;

    // Parallel prologue (R14 lesson: never serialize on tid0)
    const float L2E = 1.4426950408889634f;
    const float sg0 = sigma[0];
    const float kscale = sqrtf(0.5f * L2E) / expf(sg0);
    bool uni = true;
    #pragma unroll
    for (int c = 1; c < CH; c++) uni &= (sigma[c] == sg0);

    // Stage x (pre-scaled, 2/thread) and Yext packed to f16x2 (8/thread)
    #pragma unroll
    for (int r = 0; r < 2; r++) {
        int i = tid + r * THREADS;
        sx[i] = kscale * cx[b * NIN + i0 + i];
    }
    #pragma unroll
    for (int r = 0; r < 8; r++) {
        int idx = tid + r * THREADS;                 // 2048 slots
        int kp = idx >> 3, c = idx & 7;
        int ig = b * NIN + i0 + kp * 2;
        float ya = (c == 0) ? 1.0f : cy[ig * 7 + (c - 1)];
        float yb = (c == 0) ? 1.0f : cy[(ig + 1) * 7 + (c - 1)];
        sYh[kp][c] = pack_h2(ya, yb);                // lo = even i, hi = odd i
    }

    const int G  = b * OG + og;
    const int G0 = b * NOUT + og * OPB;
    __syncthreads();

    if (uni) {
        // t for this lane's two A rows (outputs g and g+8 of the block tile)
        const float tk0 = kscale * t[G0 + g];
        const float tk1 = kscale * t[G0 + g + 8];

        float d0 = 0.f, d1 = 0.f, d2 = 0.f, d3 = 0.f;
        const int kbase = warp * IPW;                // warp's 64-i slice

        #pragma unroll
        for (int s = 0; s < KSTEPS; s++) {
            const int k0 = kbase + s * 16;
            // x for this lane's 4 A-columns: k = 2t, 2t+1, 2t+8, 2t+9
            float2 xa = *reinterpret_cast<const float2*>(&sx[k0 + tq * 2]);
            float2 xb = *reinterpret_cast<const float2*>(&sx[k0 + tq * 2 + 8]);
            // 8 independent exp chains (irreducible MUFU work)
            float e0 = xa.x - tk0, e1 = xa.y - tk0;
            float e2 = xb.x - tk0, e3 = xb.y - tk0;
            float f0 = xa.x - tk1, f1 = xa.y - tk1;
            float f2 = xb.x - tk1, f3 = xb.y - tk1;
            float w00 = ex2_approx(e0 * -e0);
            float w01 = ex2_approx(e1 * -e1);
            float w02 = ex2_approx(e2 * -e2);
            float w03 = ex2_approx(e3 * -e3);
            float w10 = ex2_approx(f0 * -f0);
            float w11 = ex2_approx(f1 * -f1);
            float w12 = ex2_approx(f2 * -f2);
            float w13 = ex2_approx(f3 * -f3);
            unsigned int a0 = pack_h2(w00, w01);     // row g,   cols 2t,2t+1
            unsigned int a1 = pack_h2(w10, w11);     // row g+8, cols 2t,2t+1
            unsigned int a2 = pack_h2(w02, w03);     // row g,   cols +8,+9
            unsigned int a3 = pack_h2(w12, w13);     // row g+8, cols +8,+9
            unsigned int b0 = sYh[(k0 >> 1) + tq][g];      // col g rows 2t..
            unsigned int b1 = sYh[(k0 >> 1) + 4 + tq][g];  // col g rows 2t+8..
            mma_16816(d0, d1, d2, d3, a0, a1, a2, a3, b0, b1);
        }

        // D frag: d0,d1 -> row g ch 2t,2t+1 ; d2,d3 -> row g+8 same ch
        *reinterpret_cast<float2*>(&spart[warp][g][tq * 2]) =
            make_float2(d0, d1);
        *reinterpret_cast<float2*>(&spart[warp][g + 8][tq * 2]) =
            make_float2(d2, d3);
    } else {
        // Correctness-only fallback (general sigma): scalar fp32 path.
        float betas[CH];
        #pragma unroll
        for (int c = 0; c < CH; c++) {
            float sv = expf(sigma[c]);
            betas[c] = -0.5f * L2E / (sv * sv);
        }
        float ratio[CH];
        #pragma unroll
        for (int c = 0; c < CH; c++) ratio[c] = betas[c] / betas[0];

        const int o_idx = lane & 15;
        const int ihalf = lane >> 4;                 // half of warp's slice
        const float tk = kscale * t[G0 + o_idx];
        float acc[CH];                               // canonical [den, y1..y7]
        #pragma unroll
        for (int c = 0; c < CH; c++) acc[c] = 0.0f;
        const int jb = warp * IPW + ihalf * (IPW / 2);
        for (int j = jb; j < jb + IPW / 2; j++) {
            float d = sx[j] - tk;
            float a = d * -d;                        // = beta0 * d_raw^2
            acc[0] += ex2_approx(ratio[0] * a);
            const float* yrow = &cy[(b * NIN + i0 + j) * 7];
            #pragma unroll
            for (int c = 1; c < CH; c++)
                acc[c] += yrow[c - 1] * ex2_approx(ratio[c] * a);
        }
        #pragma unroll
        for (int c = 0; c < CH; c++)
            acc[c] += __shfl_xor_sync(0xffffffffu, acc[c], 16);
        if (lane < 16) {
            float4* dst = reinterpret_cast<float4*>(&spart[warp][o_idx][0]);
            dst[0] = make_float4(acc[0], acc[1], acc[2], acc[3]);
            dst[1] = make_float4(acc[4], acc[5], acc[6], acc[7]);
        }
    }
    __syncthreads();

    // Cross-warp reduce (128 threads) -> g_part.  MMA order is channel-major
    // in spart already matches canonical [den=ch0? no: ch here = Yext slot].
    // Yext slot 0 = density (packed as c==0 above), so order is canonical.
    if (tid < OPB * CH) {
        int o = tid >> 3, c = tid & 7;
        float s = 0.0f;
        #pragma unroll
        for (int w2 = 0; w2 < WARPS; w2++) s += spart[w2][o][c];
        g_part[(G * SPLITS + split) * SLOT + o * CH + c] = s;
    }

    // ---- last-block-done gate (threadFenceReduction pattern) ----
    __threadfence();
    __syncthreads();
    if (tid == 0) {
        int old = atomicAdd(&g_count[G], 1);
        s_last = (old == SPLITS - 1);
        if (s_last) g_count[G] = 0;                  // reset for next replay
    }
    __syncthreads();
    if (!s_last) return;

    // ---- finish: sum 2 splits + normalize (128 threads, fused) ----
    if (tid < OPB * CH) {
        int o = tid >> 3, c = tid & 7;
        const float* p = &g_part[G * SPLITS * SLOT + o * CH + c];
        float s = p[0] + p[SLOT];
        float den = __shfl_sync(0xffffffffu, s, lane & ~7u);
        sagg2[o][c] = (c == 0) ? s : s / (den + 1e-8f);
    }
    __syncthreads();

    // ---- finish: out[G0+o][k] = bias[k] + sum_c agg2[c]*W[c][k] ----
    {
        int o = tid >> 4, k = tid & 15;              // 16 x 16 = 256 threads
        float v = __ldg(&bias[k]);
        #pragma unroll
        for (int c = 0; c < CH; c++) v += sagg2[o][c] * __ldg(&W[c * OC + k]);
        out[(G0 + o) * OC + k] = v;                  // coalesced
    }
}

} // namespace

extern "C" void kernel_launch(void* const* d_in, const int* in_sizes, int n_in,
                              void* d_out, int out_size) {
    const float* cx = (const float*)d_in[0];  // context_x
    const float* cy = (const float*)d_in[1];  // context_y
    const float* t  = (const float*)d_in[2];  // t
    const float* sg = (const float*)d_in[3];  // sigma
    const float* W  = (const float*)d_in[4];  // W
    const float* bi = (const float*)d_in[5];  // b
    float* out = (float*)d_out;

    convdeepset_kernel<<<BATCH * OG * SPLITS, THREADS>>>(cx, cy, t, sg, W, bi, out);
}